// round 2
// baseline (speedup 1.0000x reference)
#include <cuda_runtime.h>
#include <cstdint>

#define BB 128
#define HH 1024
#define LL 256
#define NN 64

// Scratch (device globals: no allocations allowed)
__device__ float g_k[HH * LL];                      // 1 MB  : S4D conv kernel (H,L)
__device__ float g_Wt[2 * HH * HH];                 // 8 MB  : W_out, tf32-rounded + tile-permuted
__device__ float g_y[(size_t)BB * HH * LL];         // 128 MB: post-gelu activations (tf32-rounded)

// ---------------------------------------------------------------------------
// helpers
// ---------------------------------------------------------------------------
__device__ __forceinline__ float tf32_round(float f) {
    uint32_t u;
    asm("cvt.rna.tf32.f32 %0, %1;" : "=r"(u) : "f"(f));
    return __uint_as_float(u);
}
__device__ __forceinline__ uint32_t fbits(float f) { return __float_as_uint(f); }

__device__ __forceinline__ void mma_tf32(float c[4], const uint32_t a[4], uint32_t b0, uint32_t b1) {
    asm volatile(
        "mma.sync.aligned.m16n8k8.row.col.f32.tf32.tf32.f32 "
        "{%0,%1,%2,%3}, {%4,%5,%6,%7}, {%8,%9}, {%0,%1,%2,%3};"
        : "+f"(c[0]), "+f"(c[1]), "+f"(c[2]), "+f"(c[3])
        : "r"(a[0]), "r"(a[1]), "r"(a[2]), "r"(a[3]), "r"(b0), "r"(b1));
}

__device__ __forceinline__ float gelu_tanh(float v) {
    float t = tanhf(0.7978845608028654f * (v + 0.044715f * v * v * v));
    return 0.5f * v * (1.0f + t);
}

__device__ __forceinline__ uint32_t smem_u32(const void* p) {
    return (uint32_t)__cvta_generic_to_shared(p);
}
__device__ __forceinline__ void cp_async16(uint32_t dst, const void* src) {
    asm volatile("cp.async.cg.shared.global [%0], [%1], 16;\n" :: "r"(dst), "l"(src));
}
__device__ __forceinline__ void cp_commit() { asm volatile("cp.async.commit_group;\n"); }
__device__ __forceinline__ void cp_wait0() { asm volatile("cp.async.wait_group 0;\n"); }

// ---------------------------------------------------------------------------
// Kernel 1: S4D kernel materialization
// ---------------------------------------------------------------------------
__global__ __launch_bounds__(256) void k_kernel(
    const float* __restrict__ log_dt, const float* __restrict__ A_real_log,
    const float* __restrict__ A_imag, const float* __restrict__ C_re,
    const float* __restrict__ C_im) {
    int h = blockIdx.x;
    __shared__ float sCr[NN], sCi[NN], sAr[NN], sAi[NN];
    int tid = threadIdx.x;
    if (tid < NN) {
        float dt = expf(log_dt[h]);
        float Ar = -expf(A_real_log[h * NN + tid]);
        float Ai = A_imag[h * NN + tid];
        float dAr = Ar * dt, dAi = Ai * dt;
        float er = expf(dAr), sv, cv;
        sincosf(dAi, &sv, &cv);
        float Exr = er * cv - 1.0f;
        float Exi = er * sv;
        float cr = C_re[h * NN + tid], ci = C_im[h * NN + tid];
        float nr = cr * Exr - ci * Exi;
        float ni = cr * Exi + ci * Exr;
        float den = 1.0f / (Ar * Ar + Ai * Ai);
        sCr[tid] = (nr * Ar + ni * Ai) * den;
        sCi[tid] = (ni * Ar - nr * Ai) * den;
        sAr[tid] = dAr;
        sAi[tid] = dAi;
    }
    __syncthreads();
    float l = (float)tid;
    float acc = 0.0f;
#pragma unroll 4
    for (int n = 0; n < NN; n++) {
        float mag = expf(sAr[n] * l);
        float sv, cv;
        sincosf(sAi[n] * l, &sv, &cv);
        acc += sCr[n] * (mag * cv) - sCi[n] * (mag * sv);
    }
    g_k[h * LL + tid] = 2.0f * acc;
}

// ---------------------------------------------------------------------------
// Kernel 2: tf32-round + permute W into GEMM tile layout.
// g_Wt logical layout: [hb=16][kc=64][R=128][kp=16]
//   R = T*16 + r16, T = wm*2 + half (even tiles = a-half, odd = b-half)
//   source row = hb*64 + wm*16 + r16 + half*1024
//   kp = s*8 + q*2 + e  ->  source col = kc*16 + s*8 + q + e*4
// (pairs (c, c+4) adjacent so A fragments load as float2)
// ---------------------------------------------------------------------------
__global__ __launch_bounds__(256) void wprep_kernel(const float* __restrict__ W) {
    int o = blockIdx.x * 256 + threadIdx.x;
    if (o >= 2 * HH * HH) return;
    int kp = o & 15;
    int R  = (o >> 4) & 127;
    int kc = (o >> 11) & 63;
    int hb = o >> 17;
    int s = kp >> 3, p7 = kp & 7, q = p7 >> 1, e = p7 & 1;
    int T = R >> 4, r16 = R & 15;
    int wm = T >> 1, half = T & 1;
    int row = hb * 64 + wm * 16 + r16 + half * HH;
    int col = kc * 16 + s * 8 + q + e * 4;
    g_Wt[o] = tf32_round(W[(size_t)row * HH + col]);
}

// ---------------------------------------------------------------------------
// Kernel 3: causal conv + D-skip + gelu (unchanged from passing version)
// ---------------------------------------------------------------------------
#define KIDX(i) ((i) + ((i) >> 5))

__global__ __launch_bounds__(256) void conv_kernel(const float* __restrict__ x,
                                                   const float* __restrict__ D) {
    __shared__ float kp[528];
    __shared__ float xs[4][LL];
    int h = blockIdx.x >> 5;
    int b0 = (blockIdx.x & 31) << 2;
    int tid = threadIdx.x;

    kp[KIDX(tid)] = 0.0f;
    kp[KIDX(256 + tid)] = g_k[h * LL + tid];
#pragma unroll
    for (int j = 0; j < 4; j++)
        xs[j][tid] = x[((size_t)(b0 + j) * HH + h) * LL + tid];
    __syncthreads();

    int row = tid >> 6;
    int l0 = (tid & 63) << 2;
    const float* xr = xs[row];
    float Dv = D[h];
    float a0 = Dv * xr[l0 + 0];
    float a1 = Dv * xr[l0 + 1];
    float a2 = Dv * xr[l0 + 2];
    float a3 = Dv * xr[l0 + 3];

    int B0 = 256 + l0;
    float r0 = kp[KIDX(B0 + 0)];
    float r1 = kp[KIDX(B0 + 1)];
    float r2 = kp[KIDX(B0 + 2)];
    float r3 = kp[KIDX(B0 + 3)];

#pragma unroll 4
    for (int s4 = 0; s4 < LL; s4 += 4) {
        float x0 = xr[s4 + 0];
        a0 += x0 * r0; a1 += x0 * r1; a2 += x0 * r2; a3 += x0 * r3;
        r3 = kp[KIDX(B0 - s4 - 1)];
        float x1 = xr[s4 + 1];
        a0 += x1 * r3; a1 += x1 * r0; a2 += x1 * r1; a3 += x1 * r2;
        r2 = kp[KIDX(B0 - s4 - 2)];
        float x2 = xr[s4 + 2];
        a0 += x2 * r2; a1 += x2 * r3; a2 += x2 * r0; a3 += x2 * r1;
        r1 = kp[KIDX(B0 - s4 - 3)];
        float x3 = xr[s4 + 3];
        a0 += x3 * r1; a1 += x3 * r2; a2 += x3 * r3; a3 += x3 * r0;
        r0 = kp[KIDX(B0 - s4 - 4)];
    }

    float4 v;
    v.x = tf32_round(gelu_tanh(a0));
    v.y = tf32_round(gelu_tanh(a1));
    v.z = tf32_round(gelu_tanh(a2));
    v.w = tf32_round(gelu_tanh(a3));
    *(float4*)&g_y[((size_t)(b0 + row) * HH + h) * LL + l0] = v;
}

// ---------------------------------------------------------------------------
// Kernel 4: GEMM + GLU.
// Block: 64 h-out (both GLU halves = 128 W rows) x 256 l, K in chunks of 16.
// 512 threads = 16 warps, warp grid 4(m) x 4(n), warp tile m32 x n64.
// A from pre-permuted g_Wt via cp.async double buffer (pitch 24, conflict-free).
// B (y) staged with k/k+4 row pairs interleaved (pair stride 528, conflict-free)
//   so B fragments are single LDS.64. LDG->reg prefetch overlaps compute.
// ---------------------------------------------------------------------------
#define A_FLOATS 3072               // 128 rows * pitch 24
#define B_FLOATS 4224               // 8 pair-rows * 528
#define STAGE_FLOATS (A_FLOATS + B_FLOATS)
#define GEMM_SMEM_BYTES (2 * STAGE_FLOATS * 4)

__global__ __launch_bounds__(512, 1) void gemm_glu_kernel(const float* __restrict__ bias,
                                                          float* __restrict__ out) {
    extern __shared__ float sm[];
    float* Abuf[2] = { sm, sm + STAGE_FLOATS };
    float* Bbuf[2] = { sm + A_FLOATS, sm + STAGE_FLOATS + A_FLOATS };

    int hb = blockIdx.x;
    int b  = blockIdx.y;
    int tid = threadIdx.x;
    int lane = tid & 31;
    int wid = tid >> 5;
    int wm = wid & 3;            // m: 16 h each (x2 halves)
    int wn = wid >> 2;           // n: 64 l each

    const float* yb = g_y + (size_t)b * HH * LL;
    const float* wbase = g_Wt + (size_t)hb * 64 * 2048;

    float ca[8][4], cb[8][4];
#pragma unroll
    for (int t = 0; t < 8; t++)
#pragma unroll
        for (int r = 0; r < 4; r++) { ca[t][r] = 0.0f; cb[t][r] = 0.0f; }

    // A staging: thread -> (row R = tid>>2, 16B segment seg = tid&3)
    int aR = tid >> 2, aseg = tid & 3;
    // B staging: tasks tau = tid, tid+512
    int t0_k8 = tid >> 9, t0_p = (tid >> 7) & 3, t0_cp = tid & 127;   // task 0 (tid<512 so t0_k8=0)
    int t1_k8 = (tid + 512) >> 9, t1_p = ((tid + 512) >> 7) & 3, t1_cp = tid & 127;

    // ---- prologue: stage chunk 0 ----
    {
        const float* asrc = wbase + aR * 16 + aseg * 4;
        cp_async16(smem_u32(&Abuf[0][aR * 24 + aseg * 4]), asrc);
        cp_commit();
        int k = t0_k8 * 8 + t0_p;
        float2 v0 = *(const float2*)&yb[(size_t)k * LL + t0_cp * 2];
        float2 v1 = *(const float2*)&yb[(size_t)(k + 4) * LL + t0_cp * 2];
        *(float4*)&Bbuf[0][(t0_k8 * 4 + t0_p) * 528 + t0_cp * 4] = make_float4(v0.x, v1.x, v0.y, v1.y);
        k = t1_k8 * 8 + t1_p;
        v0 = *(const float2*)&yb[(size_t)k * LL + t1_cp * 2];
        v1 = *(const float2*)&yb[(size_t)(k + 4) * LL + t1_cp * 2];
        *(float4*)&Bbuf[0][(t1_k8 * 4 + t1_p) * 528 + t1_cp * 4] = make_float4(v0.x, v1.x, v0.y, v1.y);
        cp_wait0();
        __syncthreads();
    }

    int fr = lane >> 2;             // fragment row
    int fq2 = (lane & 3) * 2;       // A pair-col offset
    int fp = lane & 3;              // B pair-row
    int fc = lane >> 2;             // B col-in-n8

#pragma unroll 1
    for (int kc = 0; kc < 64; kc++) {
        int cur = kc & 1, nxt = cur ^ 1;
        float4 pb0, pb1;
        if (kc < 63) {
            const float* asrc = wbase + (size_t)(kc + 1) * 2048 + aR * 16 + aseg * 4;
            cp_async16(smem_u32(&Abuf[nxt][aR * 24 + aseg * 4]), asrc);
            cp_commit();
            int kbase = (kc + 1) * 16;
            int k = kbase + t0_k8 * 8 + t0_p;
            float2 v0 = *(const float2*)&yb[(size_t)k * LL + t0_cp * 2];
            float2 v1 = *(const float2*)&yb[(size_t)(k + 4) * LL + t0_cp * 2];
            pb0 = make_float4(v0.x, v1.x, v0.y, v1.y);
            k = kbase + t1_k8 * 8 + t1_p;
            v0 = *(const float2*)&yb[(size_t)k * LL + t1_cp * 2];
            v1 = *(const float2*)&yb[(size_t)(k + 4) * LL + t1_cp * 2];
            pb1 = make_float4(v0.x, v1.x, v0.y, v1.y);
        }

        const float* A = Abuf[cur];
        const float* Bsm = Bbuf[cur];
#pragma unroll
        for (int s = 0; s < 2; s++) {
            uint32_t aa[4], ab[4];
            {
                const float* pa = A + (wm * 32 + fr) * 24 + s * 8 + fq2;
                float2 v = *(const float2*)pa;          aa[0] = fbits(v.x); aa[2] = fbits(v.y);
                v = *(const float2*)(pa + 8 * 24);      aa[1] = fbits(v.x); aa[3] = fbits(v.y);
                v = *(const float2*)(pa + 16 * 24);     ab[0] = fbits(v.x); ab[2] = fbits(v.y);
                v = *(const float2*)(pa + 24 * 24);     ab[1] = fbits(v.x); ab[3] = fbits(v.y);
            }
            const float* pb = Bsm + (s * 4 + fp) * 528 + (wn * 64 + fc) * 2;
#pragma unroll
            for (int t = 0; t < 8; t++) {
                float2 bv = *(const float2*)(pb + t * 16);
                uint32_t b0 = fbits(bv.x), b1 = fbits(bv.y);
                mma_tf32(ca[t], aa, b0, b1);
                mma_tf32(cb[t], ab, b0, b1);
            }
        }

        if (kc < 63) {
            *(float4*)&Bbuf[nxt][(t0_k8 * 4 + t0_p) * 528 + t0_cp * 4] = pb0;
            *(float4*)&Bbuf[nxt][(t1_k8 * 4 + t1_p) * 528 + t1_cp * 4] = pb1;
            cp_wait0();
        }
        __syncthreads();
    }

    // ---- epilogue: bias + GLU ----
    int r = lane >> 2;
    int c2 = (lane & 3) << 1;
    int h = hb * 64 + wm * 16 + r;
    float ba0 = bias[h],     bb0 = bias[h + HH];
    float ba8 = bias[h + 8], bb8 = bias[h + 8 + HH];
    size_t ob0 = ((size_t)b * HH + h) * LL;
    size_t ob8 = ob0 + (size_t)8 * LL;
#pragma unroll
    for (int t = 0; t < 8; t++) {
        int ll = wn * 64 + t * 8 + c2;
        float av, bv;
        float2 w0, w8;
        av = ca[t][0] + ba0; bv = cb[t][0] + bb0;
        w0.x = av * (1.0f / (1.0f + expf(-bv)));
        av = ca[t][1] + ba0; bv = cb[t][1] + bb0;
        w0.y = av * (1.0f / (1.0f + expf(-bv)));
        av = ca[t][2] + ba8; bv = cb[t][2] + bb8;
        w8.x = av * (1.0f / (1.0f + expf(-bv)));
        av = ca[t][3] + ba8; bv = cb[t][3] + bb8;
        w8.y = av * (1.0f / (1.0f + expf(-bv)));
        *(float2*)&out[ob0 + ll] = w0;
        *(float2*)&out[ob8 + ll] = w8;
    }
}

// ---------------------------------------------------------------------------
extern "C" void kernel_launch(void* const* d_in, const int* in_sizes, int n_in,
                              void* d_out, int out_size) {
    const float* x          = (const float*)d_in[0];
    const float* log_dt     = (const float*)d_in[1];
    const float* A_real_log = (const float*)d_in[2];
    const float* A_imag     = (const float*)d_in[3];
    const float* C_re       = (const float*)d_in[4];
    const float* C_im       = (const float*)d_in[5];
    const float* D          = (const float*)d_in[6];
    const float* W_out      = (const float*)d_in[7];
    const float* b_out      = (const float*)d_in[8];
    float* out = (float*)d_out;

    static int smem_set = 0;
    if (!smem_set) {
        cudaFuncSetAttribute(gemm_glu_kernel, cudaFuncAttributeMaxDynamicSharedMemorySize,
                             GEMM_SMEM_BYTES);
        smem_set = 1;
    }

    k_kernel<<<HH, 256>>>(log_dt, A_real_log, A_imag, C_re, C_im);
    wprep_kernel<<<(2 * HH * HH) / 256, 256>>>(W_out);
    conv_kernel<<<HH * (BB / 4), 256>>>(x, D);
    gemm_glu_kernel<<<dim3(16, BB), 512, GEMM_SMEM_BYTES>>>(b_out, out);
}

// round 3
// speedup vs baseline: 1.5375x; 1.5375x over previous
#include <cuda_runtime.h>
#include <cstdint>

#define BB 128
#define HH 1024
#define LL 256
#define NN 64

// Scratch (device globals: no allocations allowed)
__device__ float g_k[HH * LL];                      // 1 MB  : S4D conv kernel (H,L)
__device__ float g_Wt[2 * HH * HH];                 // 8 MB  : W_out, tf32-rounded + tile-permuted
__device__ float g_y[(size_t)BB * HH * LL];         // 128 MB: post-gelu activations (tf32-rounded)

// ---------------------------------------------------------------------------
// helpers
// ---------------------------------------------------------------------------
__device__ __forceinline__ float tf32_round(float f) {
    uint32_t u;
    asm("cvt.rna.tf32.f32 %0, %1;" : "=r"(u) : "f"(f));
    return __uint_as_float(u);
}
__device__ __forceinline__ uint32_t fbits(float f) { return __float_as_uint(f); }

__device__ __forceinline__ void mma_tf32(float c[4], const uint32_t a[4], uint32_t b0, uint32_t b1) {
    asm volatile(
        "mma.sync.aligned.m16n8k8.row.col.f32.tf32.tf32.f32 "
        "{%0,%1,%2,%3}, {%4,%5,%6,%7}, {%8,%9}, {%0,%1,%2,%3};"
        : "+f"(c[0]), "+f"(c[1]), "+f"(c[2]), "+f"(c[3])
        : "r"(a[0]), "r"(a[1]), "r"(a[2]), "r"(a[3]), "r"(b0), "r"(b1));
}

__device__ __forceinline__ float gelu_tanh(float v) {
    float t = tanhf(0.7978845608028654f * (v + 0.044715f * v * v * v));
    return 0.5f * v * (1.0f + t);
}

__device__ __forceinline__ uint32_t smem_u32(const void* p) {
    return (uint32_t)__cvta_generic_to_shared(p);
}
__device__ __forceinline__ void cp_async16(uint32_t dst, const void* src) {
    asm volatile("cp.async.cg.shared.global [%0], [%1], 16;\n" :: "r"(dst), "l"(src));
}
__device__ __forceinline__ void cp_commit() { asm volatile("cp.async.commit_group;\n"); }
__device__ __forceinline__ void cp_wait0() { asm volatile("cp.async.wait_group 0;\n"); }

// ---------------------------------------------------------------------------
// Kernel 1: S4D kernel materialization
// ---------------------------------------------------------------------------
__global__ __launch_bounds__(256) void k_kernel(
    const float* __restrict__ log_dt, const float* __restrict__ A_real_log,
    const float* __restrict__ A_imag, const float* __restrict__ C_re,
    const float* __restrict__ C_im) {
    int h = blockIdx.x;
    __shared__ float sCr[NN], sCi[NN], sAr[NN], sAi[NN];
    int tid = threadIdx.x;
    if (tid < NN) {
        float dt = expf(log_dt[h]);
        float Ar = -expf(A_real_log[h * NN + tid]);
        float Ai = A_imag[h * NN + tid];
        float dAr = Ar * dt, dAi = Ai * dt;
        float er = expf(dAr), sv, cv;
        sincosf(dAi, &sv, &cv);
        float Exr = er * cv - 1.0f;
        float Exi = er * sv;
        float cr = C_re[h * NN + tid], ci = C_im[h * NN + tid];
        float nr = cr * Exr - ci * Exi;
        float ni = cr * Exi + ci * Exr;
        float den = 1.0f / (Ar * Ar + Ai * Ai);
        sCr[tid] = (nr * Ar + ni * Ai) * den;
        sCi[tid] = (ni * Ar - nr * Ai) * den;
        sAr[tid] = dAr;
        sAi[tid] = dAi;
    }
    __syncthreads();
    float l = (float)tid;
    float acc = 0.0f;
#pragma unroll 4
    for (int n = 0; n < NN; n++) {
        float mag = expf(sAr[n] * l);
        float sv, cv;
        sincosf(sAi[n] * l, &sv, &cv);
        acc += sCr[n] * (mag * cv) - sCi[n] * (mag * sv);
    }
    g_k[h * LL + tid] = 2.0f * acc;
}

// ---------------------------------------------------------------------------
// Kernel 2: tf32-round + permute W into GEMM tile layout (validated in R2).
// g_Wt layout: [hb=16][kc=64][R=128][kp=16]
//   R = T*16 + r16, T = wm*2 + half  (source row = hb*64 + wm*16 + r16 + half*1024)
//   kp = s*8 + q*2 + e               (source col = kc*16 + s*8 + q + e*4)
// ---------------------------------------------------------------------------
__global__ __launch_bounds__(256) void wprep_kernel(const float* __restrict__ W) {
    int o = blockIdx.x * 256 + threadIdx.x;
    if (o >= 2 * HH * HH) return;
    int kp = o & 15;
    int R  = (o >> 4) & 127;
    int kc = (o >> 11) & 63;
    int hb = o >> 17;
    int s = kp >> 3, p7 = kp & 7, q = p7 >> 1, e = p7 & 1;
    int T = R >> 4, r16 = R & 15;
    int wm = T >> 1, half = T & 1;
    int row = hb * 64 + wm * 16 + r16 + half * HH;
    int col = kc * 16 + s * 8 + q + e * 4;
    g_Wt[o] = tf32_round(W[(size_t)row * HH + col]);
}

// ---------------------------------------------------------------------------
// Kernel 3: causal conv + D-skip + gelu, with per-warp causal early exit.
// ---------------------------------------------------------------------------
#define KIDX(i) ((i) + ((i) >> 5))

__global__ __launch_bounds__(256) void conv_kernel(const float* __restrict__ x,
                                                   const float* __restrict__ D) {
    __shared__ float kp[528];
    __shared__ float xs[4][LL];
    int h = blockIdx.x >> 5;
    int b0 = (blockIdx.x & 31) << 2;
    int tid = threadIdx.x;

    kp[KIDX(tid)] = 0.0f;
    kp[KIDX(256 + tid)] = g_k[h * LL + tid];
#pragma unroll
    for (int j = 0; j < 4; j++)
        xs[j][tid] = x[((size_t)(b0 + j) * HH + h) * LL + tid];
    __syncthreads();

    int row = tid >> 6;
    int l0 = (tid & 63) << 2;
    const float* xr = xs[row];
    float Dv = D[h];
    float a0 = Dv * xr[l0 + 0];
    float a1 = Dv * xr[l0 + 1];
    float a2 = Dv * xr[l0 + 2];
    float a3 = Dv * xr[l0 + 3];

    int B0 = 256 + l0;
    float r0 = kp[KIDX(B0 + 0)];
    float r1 = kp[KIDX(B0 + 1)];
    float r2 = kp[KIDX(B0 + 2)];
    float r3 = kp[KIDX(B0 + 3)];

    // causal bound: max l covered by this warp (all s beyond hit zero-pad)
    int lmax = (((tid | 31) & 63) << 2) + 3;

#pragma unroll 4
    for (int s4 = 0; s4 <= lmax; s4 += 4) {
        float x0 = xr[s4 + 0];
        a0 += x0 * r0; a1 += x0 * r1; a2 += x0 * r2; a3 += x0 * r3;
        r3 = kp[KIDX(B0 - s4 - 1)];
        float x1 = xr[s4 + 1];
        a0 += x1 * r3; a1 += x1 * r0; a2 += x1 * r1; a3 += x1 * r2;
        r2 = kp[KIDX(B0 - s4 - 2)];
        float x2 = xr[s4 + 2];
        a0 += x2 * r2; a1 += x2 * r3; a2 += x2 * r0; a3 += x2 * r1;
        r1 = kp[KIDX(B0 - s4 - 3)];
        float x3 = xr[s4 + 3];
        a0 += x3 * r1; a1 += x3 * r2; a2 += x3 * r3; a3 += x3 * r0;
        r0 = kp[KIDX(B0 - s4 - 4)];
    }

    float4 v;
    v.x = tf32_round(gelu_tanh(a0));
    v.y = tf32_round(gelu_tanh(a1));
    v.z = tf32_round(gelu_tanh(a2));
    v.w = tf32_round(gelu_tanh(a3));
    *(float4*)&g_y[((size_t)(b0 + row) * HH + h) * LL + l0] = v;
}

// ---------------------------------------------------------------------------
// Kernel 4: GEMM + GLU.
// Block: 64 h-out (both GLU halves) x 128 l, K chunks of 16. 256 thr, 8 warps
// = 4(m) x 2(n); warp tile m32(16a+16b) x n64. Double-buffered:
// A via cp.async from permuted g_Wt (pitch 24, conflict-free),
// B LDG->STS pair-interleaved (pair-row pitch 264 == 8 mod 32, conflict-free).
// ---------------------------------------------------------------------------
#define A_PITCH 24
#define B_PITCH 264
#define A_FLOATS (128 * A_PITCH)            // 3072
#define B_FLOATS (8 * B_PITCH)              // 2112
#define STAGE (A_FLOATS + B_FLOATS)         // 5184 floats
#define GEMM_SMEM_BYTES (2 * STAGE * 4)     // 41472 B

__global__ __launch_bounds__(256, 2) void gemm_glu_kernel(const float* __restrict__ bias,
                                                          float* __restrict__ out) {
    extern __shared__ float sm[];

    int lblk = blockIdx.x;          // 0..1  (128 l each)
    int hb   = blockIdx.y;          // 0..15 (64 h each)
    int b    = blockIdx.z;          // batch
    int tid = threadIdx.x;
    int lane = tid & 31;
    int wid = tid >> 5;
    int wm = wid & 3;               // 16 h (x2 halves)
    int wn = wid >> 2;              // 64 l

    float ca[8][4], cb[8][4];
#pragma unroll
    for (int t = 0; t < 8; t++)
#pragma unroll
        for (int r = 0; r < 4; r++) { ca[t][r] = 0.0f; cb[t][r] = 0.0f; }

    // ---- staging descriptors (computed once) ----
    // A: tasks (aR, aseg) and (aR+64, aseg)
    int aR = tid >> 2, aseg = tid & 3;
    const float* aSrc = g_Wt + (size_t)hb * 131072 + aR * 16 + aseg * 4;   // +=2048/chunk
    uint32_t aDst0 = smem_u32(sm + aR * A_PITCH + aseg * 4);
    uint32_t aDst0b = aDst0 + 64 * A_PITCH * 4;
    uint32_t aDst1 = aDst0 + STAGE * 4;
    uint32_t aDst1b = aDst0b + STAGE * 4;

    // B: tasks pr = tid>>6 and pr+4, col-pair cp = tid&63
    const float* yb = g_y + (size_t)b * HH * LL + lblk * 128;
    int pr0 = tid >> 6;             // 0..3  (s=0, p=pr0)
    int cp  = tid & 63;
    const float* bSrc0 = yb + pr0 * LL + cp * 2;          // rows p, p+4
    const float* bSrc1 = yb + (8 + pr0) * LL + cp * 2;    // rows 8+p, 12+p
    float* bDst0 = sm + A_FLOATS + pr0 * B_PITCH + cp * 4;
    float* bDst0b = bDst0 + 4 * B_PITCH;
    float* bDst1 = bDst0 + STAGE;
    float* bDst1b = bDst0b + STAGE;

    // ---- fragment read bases (per warp, per buffer) ----
    int fr = lane >> 2;             // 0..7
    int fq2 = (lane & 3) * 2;
    int fp = lane & 3;
    int fc = lane >> 2;
    const float* pA0 = sm + (wm * 32 + fr) * A_PITCH + fq2;
    const float* pA1 = pA0 + STAGE;
    const float* pB0 = sm + A_FLOATS + fp * B_PITCH + (wn * 64 + fc) * 2;
    const float* pB1 = pB0 + STAGE;

    // ---- prologue: stage chunk 0 into buffer 0 ----
    {
        cp_async16(aDst0, aSrc);
        cp_async16(aDst0b, aSrc + 64 * 16);
        cp_commit();
        float2 v0 = *(const float2*)bSrc0;
        float2 v1 = *(const float2*)(bSrc0 + 4 * LL);
        *(float4*)bDst0 = make_float4(v0.x, v1.x, v0.y, v1.y);
        v0 = *(const float2*)bSrc1;
        v1 = *(const float2*)(bSrc1 + 4 * LL);
        *(float4*)bDst0b = make_float4(v0.x, v1.x, v0.y, v1.y);
        aSrc += 2048;
        bSrc0 += 16 * LL;
        bSrc1 += 16 * LL;
        cp_wait0();
        __syncthreads();
    }

#pragma unroll 1
    for (int kc = 0; kc < 64; kc++) {
        int cur = kc & 1;
        float4 rb0, rb1;
        if (kc < 63) {
            cp_async16(cur ? aDst0 : aDst1, aSrc);
            cp_async16(cur ? aDst0b : aDst1b, aSrc + 64 * 16);
            cp_commit();
            aSrc += 2048;
            float2 v0 = *(const float2*)bSrc0;
            float2 v1 = *(const float2*)(bSrc0 + 4 * LL);
            rb0 = make_float4(v0.x, v1.x, v0.y, v1.y);
            v0 = *(const float2*)bSrc1;
            v1 = *(const float2*)(bSrc1 + 4 * LL);
            rb1 = make_float4(v0.x, v1.x, v0.y, v1.y);
            bSrc0 += 16 * LL;
            bSrc1 += 16 * LL;
        }

        const float* Ac = cur ? pA1 : pA0;
        const float* Bc = cur ? pB1 : pB0;
#pragma unroll
        for (int s = 0; s < 2; s++) {
            uint32_t aa[4], ab[4];
            const float* pa = Ac + s * 8;
            float2 v = *(const float2*)pa;                  aa[0] = fbits(v.x); aa[2] = fbits(v.y);
            v = *(const float2*)(pa + 8 * A_PITCH);         aa[1] = fbits(v.x); aa[3] = fbits(v.y);
            v = *(const float2*)(pa + 16 * A_PITCH);        ab[0] = fbits(v.x); ab[2] = fbits(v.y);
            v = *(const float2*)(pa + 24 * A_PITCH);        ab[1] = fbits(v.x); ab[3] = fbits(v.y);
            const float* pb = Bc + s * 4 * B_PITCH;
#pragma unroll
            for (int t = 0; t < 8; t++) {
                float2 bv = *(const float2*)(pb + t * 16);
                uint32_t b0 = fbits(bv.x), b1 = fbits(bv.y);
                mma_tf32(ca[t], aa, b0, b1);
                mma_tf32(cb[t], ab, b0, b1);
            }
        }

        if (kc < 63) {
            *(float4*)(cur ? bDst0 : bDst1) = rb0;
            *(float4*)(cur ? bDst0b : bDst1b) = rb1;
            cp_wait0();
        }
        __syncthreads();
    }

    // ---- epilogue: bias + GLU ----
    int r = lane >> 2;
    int c2 = (lane & 3) << 1;
    int h = hb * 64 + wm * 16 + r;
    float ba0 = bias[h],     bb0 = bias[h + HH];
    float ba8 = bias[h + 8], bb8 = bias[h + 8 + HH];
    size_t ob0 = ((size_t)b * HH + h) * LL;
    size_t ob8 = ob0 + (size_t)8 * LL;
#pragma unroll
    for (int t = 0; t < 8; t++) {
        int ll = lblk * 128 + wn * 64 + t * 8 + c2;
        float av, bv;
        float2 w0, w8;
        av = ca[t][0] + ba0; bv = cb[t][0] + bb0;
        w0.x = av * (1.0f / (1.0f + expf(-bv)));
        av = ca[t][1] + ba0; bv = cb[t][1] + bb0;
        w0.y = av * (1.0f / (1.0f + expf(-bv)));
        av = ca[t][2] + ba8; bv = cb[t][2] + bb8;
        w8.x = av * (1.0f / (1.0f + expf(-bv)));
        av = ca[t][3] + ba8; bv = cb[t][3] + bb8;
        w8.y = av * (1.0f / (1.0f + expf(-bv)));
        *(float2*)&out[ob0 + ll] = w0;
        *(float2*)&out[ob8 + ll] = w8;
    }
}

// ---------------------------------------------------------------------------
extern "C" void kernel_launch(void* const* d_in, const int* in_sizes, int n_in,
                              void* d_out, int out_size) {
    const float* x          = (const float*)d_in[0];
    const float* log_dt     = (const float*)d_in[1];
    const float* A_real_log = (const float*)d_in[2];
    const float* A_imag     = (const float*)d_in[3];
    const float* C_re       = (const float*)d_in[4];
    const float* C_im       = (const float*)d_in[5];
    const float* D          = (const float*)d_in[6];
    const float* W_out      = (const float*)d_in[7];
    const float* b_out      = (const float*)d_in[8];
    float* out = (float*)d_out;

    k_kernel<<<HH, 256>>>(log_dt, A_real_log, A_imag, C_re, C_im);
    wprep_kernel<<<(2 * HH * HH) / 256, 256>>>(W_out);
    conv_kernel<<<HH * (BB / 4), 256>>>(x, D);
    gemm_glu_kernel<<<dim3(2, 16, BB), 256, GEMM_SMEM_BYTES>>>(b_out, out);
}